// round 1
// baseline (speedup 1.0000x reference)
#include <cuda_runtime.h>
#include <cuda_bf16.h>
#include <math.h>

// total = sum_i [ 0.5*w^2 - 0.5*((w-mu)/sig)^2 - log(sig) ]        (weights)
//       + sum_j [ 0.5*((y-mup)/sp)^2 ]                              (likelihood, negated)
//       + B * (log(sp) + HALF_LOG_2PI)                              (closed-form constant)
// (HALF_LOG_2PI cancels between variational and prior terms; PRIOR_SIGMA=1.)

#define HALF_LOG_2PI 0.9189385332046727

static constexpr int BLOCKS  = 2048;
static constexpr int THREADS = 256;

__device__ double g_partials[BLOCKS];

__device__ __forceinline__ float term5(float w, float mu, float sg,
                                       float mp, float yt, float inv_sp) {
    float z = (w - mu) * __frcp_rn(sg);
    float u = (yt - mp) * inv_sp;
    return 0.5f * w * w - 0.5f * z * z - __logf(sg) + 0.5f * u * u;
}

__global__ __launch_bounds__(THREADS, 8)
void fused_reduce_kernel(const float4* __restrict__ w,
                         const float4* __restrict__ mu,
                         const float4* __restrict__ sg,
                         const float4* __restrict__ mp,
                         const float4* __restrict__ yt,
                         const float*  __restrict__ sp_ptr,
                         int n4) {
    const float inv_sp = __frcp_rn(*sp_ptr);

    float acc = 0.0f;
    int stride = gridDim.x * blockDim.x;
    for (int i = blockIdx.x * blockDim.x + threadIdx.x; i < n4; i += stride) {
        float4 a = __ldg(&w[i]);
        float4 b = __ldg(&mu[i]);
        float4 c = __ldg(&sg[i]);
        float4 d = __ldg(&mp[i]);
        float4 e = __ldg(&yt[i]);
        acc += term5(a.x, b.x, c.x, d.x, e.x, inv_sp);
        acc += term5(a.y, b.y, c.y, d.y, e.y, inv_sp);
        acc += term5(a.z, b.z, c.z, d.z, e.z, inv_sp);
        acc += term5(a.w, b.w, c.w, d.w, e.w, inv_sp);
    }

    // warp reduce (float is plenty for <=64 terms per thread)
    #pragma unroll
    for (int off = 16; off > 0; off >>= 1)
        acc += __shfl_xor_sync(0xFFFFFFFFu, acc, off);

    __shared__ double s_warp[THREADS / 32];
    int lane = threadIdx.x & 31;
    int wid  = threadIdx.x >> 5;
    if (lane == 0) s_warp[wid] = (double)acc;
    __syncthreads();

    if (threadIdx.x == 0) {
        double bsum = 0.0;
        #pragma unroll
        for (int k = 0; k < THREADS / 32; k++) bsum += s_warp[k];
        g_partials[blockIdx.x] = bsum;
    }
}

__global__ void final_reduce_kernel(const float* __restrict__ sp_ptr,
                                    float* __restrict__ out,
                                    int n_batch) {
    __shared__ double s[THREADS];
    double acc = 0.0;
    for (int i = threadIdx.x; i < BLOCKS; i += THREADS)
        acc += g_partials[i];
    s[threadIdx.x] = acc;
    __syncthreads();
    for (int ofs = THREADS / 2; ofs > 0; ofs >>= 1) {
        if (threadIdx.x < ofs) s[threadIdx.x] += s[threadIdx.x + ofs];
        __syncthreads();
    }
    if (threadIdx.x == 0) {
        double sp = (double)(*sp_ptr);
        double c  = (double)n_batch * (log(sp) + HALF_LOG_2PI);
        out[0] = (float)(s[0] + c);
    }
}

extern "C" void kernel_launch(void* const* d_in, const int* in_sizes, int n_in,
                              void* d_out, int out_size) {
    // metadata order: noisy_weights, mu_weights, sigma_weights,
    //                 mu_prediction, sigma_prediction (scalar), y_true
    const float4* w  = (const float4*)d_in[0];
    const float4* mu = (const float4*)d_in[1];
    const float4* sg = (const float4*)d_in[2];
    const float4* mp = (const float4*)d_in[3];
    const float*  sp = (const float*) d_in[4];
    const float4* yt = (const float4*)d_in[5];

    int n  = in_sizes[0];      // 2^24, divisible by 4
    int n4 = n >> 2;

    fused_reduce_kernel<<<BLOCKS, THREADS>>>(w, mu, sg, mp, yt, sp, n4);
    final_reduce_kernel<<<1, THREADS>>>(sp, (float*)d_out, in_sizes[5]);
}